// round 13
// baseline (speedup 1.0000x reference)
#include <cuda_runtime.h>
#include <cuda_bf16.h>
#include <cstdint>

#define N_NODES 100000
#define N_EDGES 1600000
#define IN_F    64
#define HID     128
#define N_CLS   10

#define NB_NODES ((N_NODES + 255) / 256)     // 391
#define NB_E4    (N_EDGES / 4 / 256 + 1)     // 1563
#define N_QUADS  (N_EDGES / 4)               // 400000
#define NB_CVT   (N_NODES * IN_F / (256*4))  // 6250
#define NB_W1    16
#define NB_W2    4

#define MLP_BLOCKS ((N_NODES + 127) / 128)   // 782

// ---------------- device scratch ----------------
__device__ int            g_deg[N_NODES];    // zero-init; re-zeroed by k_fill
__device__ int            g_ptr[N_NODES + 1];
__device__ float          g_dis[N_NODES];
__device__ int            g_srcs[N_EDGES];
__device__ unsigned short g_rank[N_EDGES];
__device__ int            g_bsum[NB_NODES];
__device__ unsigned       g_sync;            // scan grid-barrier counter (reset by k_fill)
__device__ unsigned       g_xh[(size_t)N_NODES * 32];  // xs = dis*x, bf16x2 (12.8 MB)
__device__ unsigned       g_aggh[(size_t)N_NODES * 32];// \hat{A}x bf16x2 (12.8 MB)
__device__ unsigned       g_w1p[32 * 128];
__device__ unsigned       g_w2p[64 * 16];
__device__ unsigned       g_zh[(size_t)N_NODES * 8];   // zs = dis*z, bf16, 16-col pad
__device__ float          g_part[NB_NODES * 11];
__device__ unsigned       g_done;

__device__ __forceinline__ unsigned packbf(float a, float b) {
    __nv_bfloat162 t = __floats2bfloat162_rn(a, b);
    return *(unsigned*)&t;
}
__device__ __forceinline__ float2 unpackbf(unsigned u) {
    return __bfloat1622float2(*(__nv_bfloat162*)&u);
}
__device__ __forceinline__ uint32_t su32(const void* p) {
    return (uint32_t)__cvta_generic_to_shared(p);
}
__device__ __forceinline__ void ldmatrix4(uint32_t& a0, uint32_t& a1, uint32_t& a2, uint32_t& a3, uint32_t addr) {
    asm volatile("ldmatrix.sync.aligned.m8n8.x4.shared.b16 {%0,%1,%2,%3}, [%4];"
                 : "=r"(a0), "=r"(a1), "=r"(a2), "=r"(a3) : "r"(addr));
}
__device__ __forceinline__ void mma16816(float* c, uint32_t a0, uint32_t a1, uint32_t a2, uint32_t a3,
                                         uint32_t b0, uint32_t b1) {
    asm volatile("mma.sync.aligned.m16n8k16.row.col.f32.bf16.bf16.f32 "
                 "{%0,%1,%2,%3},{%4,%5,%6,%7},{%8,%9},{%0,%1,%2,%3};"
                 : "+f"(c[0]), "+f"(c[1]), "+f"(c[2]), "+f"(c[3])
                 : "r"(a0), "r"(a1), "r"(a2), "r"(a3), "r"(b0), "r"(b1));
}

// ---------------- K1: degree histogram (4 edges/thread, ranks) + W pack ------
__global__ void k_pre(const int* __restrict__ ei,
                      const float* __restrict__ W1, const float* __restrict__ W2) {
    int b = blockIdx.x;
    if (b < NB_E4) {
        int q = b * 256 + threadIdx.x;
        if (q < N_QUADS) {
            int4 c = ((const int4*)(ei + N_EDGES))[q];
            int rk[4];
            rk[0] = ((unsigned)c.x < (unsigned)N_NODES) ? atomicAdd(&g_deg[c.x], 1) : 0;
            rk[1] = ((unsigned)c.y < (unsigned)N_NODES) ? atomicAdd(&g_deg[c.y], 1) : 0;
            rk[2] = ((unsigned)c.z < (unsigned)N_NODES) ? atomicAdd(&g_deg[c.z], 1) : 0;
            rk[3] = ((unsigned)c.w < (unsigned)N_NODES) ? atomicAdd(&g_deg[c.w], 1) : 0;
            ushort4 r4;
            r4.x = (unsigned short)rk[0];
            r4.y = (unsigned short)rk[1];
            r4.z = (unsigned short)rk[2];
            r4.w = (unsigned short)rk[3];
            ((ushort4*)g_rank)[q] = r4;
        }
    } else if (b < NB_E4 + NB_W1) {
        int t = (b - NB_E4) * 256 + threadIdx.x;
        int k2 = t >> 7, n = t & 127;
        g_w1p[t] = packbf(W1[(2 * k2) * HID + n], W1[(2 * k2 + 1) * HID + n]);
    } else {
        int t = (b - NB_E4 - NB_W1) * 256 + threadIdx.x;
        int k2 = t >> 4, n = t & 15;
        unsigned v = 0;
        if (n < N_CLS)
            v = packbf(W2[(2 * k2) * N_CLS + n], W2[(2 * k2 + 1) * N_CLS + n]);
        g_w2p[t] = v;
    }
}

// ---------------- K2: FUSED scan (block sums + grid barrier + prefix) --------
__global__ void k_scan() {
    const int tid = threadIdx.x, lane = tid & 31, wid = tid >> 5;
    const int b = blockIdx.x;
    int i = b * 256 + tid;
    int v = (i < N_NODES) ? g_deg[i] : 0;

    int s1 = v;
    #pragma unroll
    for (int o = 16; o > 0; o >>= 1) s1 += __shfl_xor_sync(0xffffffffu, s1, o);
    __shared__ int ws[8];
    __shared__ int wpre[8];
    __shared__ int s_pre;
    if (lane == 0) ws[wid] = s1;
    __syncthreads();
    if (tid == 0) {
        int s = 0;
        #pragma unroll
        for (int w = 0; w < 8; w++) s += ws[w];
        g_bsum[b] = s;
        __threadfence();
        atomicAdd(&g_sync, 1u);
        while (*(volatile unsigned*)&g_sync < (unsigned)NB_NODES) { }
    }
    __syncthreads();
    __threadfence();

    int pre = 0;
    for (int bb = tid; bb < b; bb += 256) pre += __ldcg(&g_bsum[bb]);
    #pragma unroll
    for (int o = 16; o > 0; o >>= 1) pre += __shfl_xor_sync(0xffffffffu, pre, o);
    if (lane == 0) wpre[wid] = pre;
    __syncthreads();
    if (tid == 0) {
        int s = 0;
        #pragma unroll
        for (int w = 0; w < 8; w++) s += wpre[w];
        s_pre = s;
    }
    __syncthreads();
    int prefix = s_pre;

    int x = v;
    #pragma unroll
    for (int o = 1; o < 32; o <<= 1) {
        int t = __shfl_up_sync(0xffffffffu, x, o);
        if (lane >= o) x += t;
    }
    if (lane == 31) ws[wid] = x;
    __syncthreads();
    if (wid == 0 && lane < 8) {
        int t = ws[lane];
        #pragma unroll
        for (int o = 1; o < 8; o <<= 1) {
            int u = __shfl_up_sync(0x000000ffu, t, o);
            if (lane >= o) t += u;
        }
        ws[lane] = t;
    }
    __syncthreads();
    int incl = x + (wid > 0 ? ws[wid - 1] : 0);
    int excl = prefix + incl - v;
    if (i < N_NODES) {
        g_ptr[i] = excl;
        g_dis[i] = rsqrtf((float)(v + 1));
    }
    if (b == NB_NODES - 1 && tid == 255)
        g_ptr[N_NODES] = prefix + incl;
}

// ---------------- K3: atomic-free CSR fill (4 edges/thread) + bf16 convert ---
__global__ void k_fill(const int* __restrict__ ei, const float* __restrict__ x) {
    int b = blockIdx.x;
    if (b < NB_E4) {
        int q = b * 256 + threadIdx.x;
        if (q < N_NODES) g_deg[q] = 0;         // reset for next replay
        if (q == N_QUADS) g_sync = 0;          // reset scan barrier counter
        if (q < N_QUADS) {
            int4 r = ((const int4*)ei)[q];
            int4 c = ((const int4*)(ei + N_EDGES))[q];
            ushort4 rk = ((const ushort4*)g_rank)[q];
            int p0 = ((unsigned)c.x < (unsigned)N_NODES) ? g_ptr[c.x] + rk.x : -1;
            int p1 = ((unsigned)c.y < (unsigned)N_NODES) ? g_ptr[c.y] + rk.y : -1;
            int p2 = ((unsigned)c.z < (unsigned)N_NODES) ? g_ptr[c.z] + rk.z : -1;
            int p3 = ((unsigned)c.w < (unsigned)N_NODES) ? g_ptr[c.w] + rk.w : -1;
            if (p0 >= 0 && (unsigned)r.x < (unsigned)N_NODES) g_srcs[p0] = r.x;
            if (p1 >= 0 && (unsigned)r.y < (unsigned)N_NODES) g_srcs[p1] = r.y;
            if (p2 >= 0 && (unsigned)r.z < (unsigned)N_NODES) g_srcs[p2] = r.z;
            if (p3 >= 0 && (unsigned)r.w < (unsigned)N_NODES) g_srcs[p3] = r.w;
        }
    } else {
        int i = (b - NB_E4) * 256 + threadIdx.x;   // 1.6M threads, 4 floats each
        float d = g_dis[i >> 4];
        float4 v = ((const float4*)x)[i];
        uint2 pk;
        pk.x = packbf(d * v.x, d * v.y);
        pk.y = packbf(d * v.z, d * v.w);
        ((uint2*)g_xh)[i] = pk;
    }
}

// ---------------- K4: agg_i = d_i * (xs_i + sum_r xs_r)  (bf16, min instr) ---
__global__ void k_aggx() {
    int warp = (blockIdx.x * blockDim.x + threadIdx.x) >> 5;
    int lane = threadIdx.x & 31;
    if (warp >= N_NODES) return;
    float di = g_dis[warp];
    float2 acc = unpackbf(g_xh[(size_t)warp * 32 + lane]);   // xs_i (self-loop)
    int p = g_ptr[warp], e = g_ptr[warp + 1];
    for (; p + 16 <= e; p += 16) {
        int r[16];
        #pragma unroll
        for (int j = 0; j < 16; j++) r[j] = g_srcs[p + j];
        unsigned u[16];
        #pragma unroll
        for (int j = 0; j < 16; j++) u[j] = g_xh[(size_t)r[j] * 32 + lane];
        #pragma unroll
        for (int j = 0; j < 16; j++) {
            float2 t = unpackbf(u[j]);
            acc.x += t.x; acc.y += t.y;
        }
    }
    for (; p + 4 <= e; p += 4) {
        int r[4];
        #pragma unroll
        for (int j = 0; j < 4; j++) r[j] = g_srcs[p + j];
        unsigned u[4];
        #pragma unroll
        for (int j = 0; j < 4; j++) u[j] = g_xh[(size_t)r[j] * 32 + lane];
        #pragma unroll
        for (int j = 0; j < 4; j++) {
            float2 t = unpackbf(u[j]);
            acc.x += t.x; acc.y += t.y;
        }
    }
    for (; p < e; ++p) {
        int r = g_srcs[p];
        float2 t = unpackbf(g_xh[(size_t)r * 32 + lane]);
        acc.x += t.x; acc.y += t.y;
    }
    g_aggh[(size_t)warp * 32 + lane] = packbf(di * acc.x, di * acc.y);
}

// ---------------- K5: tensor-core MLP; z written premultiplied by dis --------
#define SA_STRIDE 136
#define W1_STRIDE 136
#define W2_STRIDE 40
#define SMEM_MLP ((32*W1_STRIDE + 64*W2_STRIDE + 128) * 4 + 128 * SA_STRIDE * 2)

__global__ void __launch_bounds__(256) k_mlp(const float* __restrict__ b1) {
    extern __shared__ __align__(16) unsigned char smem_raw[];
    unsigned* sW1p = (unsigned*)smem_raw;
    unsigned* sW2p = sW1p + 32 * W1_STRIDE;
    float*    sb1  = (float*)(sW2p + 64 * W2_STRIDE);
    __nv_bfloat16* sAh = (__nv_bfloat16*)(sb1 + 128);

    const int tid = threadIdx.x;
    const int w = tid >> 5, l = tid & 31;
    const int row0 = blockIdx.x * 128;

    for (int t = tid; t < 32 * 128; t += 256)
        sW1p[(t >> 7) * W1_STRIDE + (t & 127)] = g_w1p[t];
    for (int t = tid; t < 64 * 16; t += 256)
        sW2p[(t >> 4) * W2_STRIDE + (t & 15)] = g_w2p[t];
    if (tid < 128) sb1[tid] = b1[tid];
    for (int t = tid; t < 1024; t += 256) {
        int row = t >> 3, q = t & 7;
        int gr = row0 + row;
        uint4 v = make_uint4(0, 0, 0, 0);
        if (gr < N_NODES) v = ((const uint4*)g_aggh)[(size_t)gr * 8 + q];
        *(uint4*)((char*)sAh + row * (SA_STRIDE * 2) + q * 16) = v;
    }
    __syncthreads();

    const int lrow = l >> 2;
    const int colb = (l & 3) * 2;
    const int nb = l >> 2;
    const uint32_t a_base = su32(sAh) + (uint32_t)(((w * 16 + (l & 15)) * SA_STRIDE + ((l >> 4) * 8)) * 2);

    float acc[16][4];
    #pragma unroll
    for (int nt = 0; nt < 16; nt++)
        #pragma unroll
        for (int j = 0; j < 4; j++) acc[nt][j] = 0.f;

    #pragma unroll
    for (int kk = 0; kk < 4; kk++) {
        uint32_t a0, a1, a2, a3;
        ldmatrix4(a0, a1, a2, a3, a_base + kk * 32);
        int k2b = kk * 8 + (l & 3);
        #pragma unroll
        for (int nt = 0; nt < 16; nt++) {
            unsigned bf0 = sW1p[k2b * W1_STRIDE + nt * 8 + nb];
            unsigned bf1 = sW1p[(k2b + 4) * W1_STRIDE + nt * 8 + nb];
            mma16816(acc[nt], a0, a1, a2, a3, bf0, bf1);
        }
    }
    __syncthreads();

    const int hrow0 = w * 16 + lrow;
    #pragma unroll
    for (int nt = 0; nt < 16; nt++) {
        float bb0 = sb1[nt * 8 + colb];
        float bb1 = sb1[nt * 8 + colb + 1];
        float c0 = fmaxf(acc[nt][0] + bb0, 0.f);
        float c1 = fmaxf(acc[nt][1] + bb1, 0.f);
        float c2 = fmaxf(acc[nt][2] + bb0, 0.f);
        float c3 = fmaxf(acc[nt][3] + bb1, 0.f);
        *(unsigned*)((char*)sAh + (hrow0 * SA_STRIDE + nt * 8 + colb) * 2) = packbf(c0, c1);
        *(unsigned*)((char*)sAh + ((hrow0 + 8) * SA_STRIDE + nt * 8 + colb) * 2) = packbf(c2, c3);
    }
    __syncwarp();

    float acc2[2][4];
    #pragma unroll
    for (int nt = 0; nt < 2; nt++)
        #pragma unroll
        for (int j = 0; j < 4; j++) acc2[nt][j] = 0.f;

    #pragma unroll
    for (int kk = 0; kk < 8; kk++) {
        uint32_t a0, a1, a2, a3;
        ldmatrix4(a0, a1, a2, a3, a_base + kk * 32);
        int k2b = kk * 8 + (l & 3);
        #pragma unroll
        for (int nt = 0; nt < 2; nt++) {
            unsigned bf0 = sW2p[k2b * W2_STRIDE + nt * 8 + nb];
            unsigned bf1 = sW2p[(k2b + 4) * W2_STRIDE + nt * 8 + nb];
            mma16816(acc2[nt], a0, a1, a2, a3, bf0, bf1);
        }
    }

    int gr0 = row0 + w * 16 + lrow;
    int gr1 = gr0 + 8;
    int cq = l & 3;
    if (gr0 < N_NODES) {
        float d0 = g_dis[gr0];
        g_zh[(size_t)gr0 * 8 + cq] = packbf(d0 * acc2[0][0], d0 * acc2[0][1]);
        g_zh[(size_t)gr0 * 8 + 4 + cq] = (cq == 0) ? packbf(d0 * acc2[1][0], d0 * acc2[1][1]) : 0u;
    }
    if (gr1 < N_NODES) {
        float d1 = g_dis[gr1];
        g_zh[(size_t)gr1 * 8 + cq] = packbf(d1 * acc2[0][2], d1 * acc2[0][3]);
        g_zh[(size_t)gr1 * 8 + 4 + cq] = (cq == 0) ? packbf(d1 * acc2[1][2], d1 * acc2[1][3]) : 0u;
    }
}

// ---------------- K6: a = d_i*(zs_i + sum zs_r) + b2; log_softmax; reduce ----
__device__ __forceinline__ void add_row(float* a, const uint4 v0, const uint2 v1) {
    float2 t;
    t = unpackbf(v0.x); a[0] += t.x; a[1] += t.y;
    t = unpackbf(v0.y); a[2] += t.x; a[3] += t.y;
    t = unpackbf(v0.z); a[4] += t.x; a[5] += t.y;
    t = unpackbf(v0.w); a[6] += t.x; a[7] += t.y;
    t = unpackbf(v1.x); a[8] += t.x; a[9] += t.y;
}

__global__ void k_final(const float* __restrict__ b2, float* __restrict__ out) {
    const int tid = threadIdx.x, lane = tid & 31, wid = tid >> 5;
    int i = blockIdx.x * blockDim.x + tid;
    float vals[11];
    #pragma unroll
    for (int v = 0; v < 11; v++) vals[v] = 0.f;

    if (i < N_NODES) {
        const uint4* z4 = (const uint4*)g_zh;
        const uint2* z2 = (const uint2*)g_zh;
        float di = g_dis[i];
        float a[10];
        #pragma unroll
        for (int c = 0; c < 10; c++) a[c] = 0.f;
        add_row(a, z4[(size_t)i * 2], z2[(size_t)i * 4 + 2]);
        int p = g_ptr[i], e = g_ptr[i + 1];
        for (; p + 4 <= e; p += 4) {
            int r[4];
            #pragma unroll
            for (int j = 0; j < 4; j++) r[j] = g_srcs[p + j];
            uint4 u[4];
            uint2 w4[4];
            #pragma unroll
            for (int j = 0; j < 4; j++) {
                u[j] = z4[(size_t)r[j] * 2];
                w4[j] = z2[(size_t)r[j] * 4 + 2];
            }
            #pragma unroll
            for (int j = 0; j < 4; j++) add_row(a, u[j], w4[j]);
        }
        for (; p < e; ++p) {
            int r = g_srcs[p];
            add_row(a, z4[(size_t)r * 2], z2[(size_t)r * 4 + 2]);
        }
        float mx = -1e30f;
        #pragma unroll
        for (int c = 0; c < 10; c++) { a[c] = di * a[c] + b2[c]; mx = fmaxf(mx, a[c]); }
        float se = 0.f;
        #pragma unroll
        for (int c = 0; c < 10; c++) se += expf(a[c] - mx);
        float lse = mx + logf(se);
        #pragma unroll
        for (int c = 0; c < 10; c++) vals[c] = a[c];
        vals[10] = lse;
    }

    #pragma unroll
    for (int v = 0; v < 11; v++)
        #pragma unroll
        for (int off = 16; off > 0; off >>= 1)
            vals[v] += __shfl_xor_sync(0xffffffffu, vals[v], off);

    __shared__ float sw[8][11];
    if (lane == 0)
        #pragma unroll
        for (int v = 0; v < 11; v++) sw[wid][v] = vals[v];
    __syncthreads();
    if (wid == 0) {
        #pragma unroll
        for (int v = 0; v < 11; v++) {
            float t = (lane < 8) ? sw[lane][v] : 0.f;
            #pragma unroll
            for (int off = 4; off > 0; off >>= 1)
                t += __shfl_xor_sync(0xffffffffu, t, off);
            if (lane == 0) g_part[blockIdx.x * 11 + v] = t;
        }
    }

    __shared__ bool s_last;
    __threadfence();
    if (tid == 0) {
        unsigned ticket = atomicAdd(&g_done, 1u);
        s_last = (ticket == (unsigned)(gridDim.x - 1));
        if (s_last) g_done = 0;
    }
    __syncthreads();
    if (!s_last) return;

    const volatile float* vp = (const volatile float*)g_part;
    float s[11];
    #pragma unroll
    for (int v = 0; v < 11; v++) {
        float t = 0.f;
        for (int b = tid; b < NB_NODES; b += 256) t += vp[b * 11 + v];
        s[v] = t;
    }
    #pragma unroll
    for (int v = 0; v < 11; v++)
        #pragma unroll
        for (int off = 16; off > 0; off >>= 1)
            s[v] += __shfl_xor_sync(0xffffffffu, s[v], off);

    __shared__ float sw2[8][11];
    __shared__ float tot[11];
    if (lane == 0)
        #pragma unroll
        for (int v = 0; v < 11; v++) sw2[wid][v] = s[v];
    __syncthreads();
    if (wid == 0) {
        #pragma unroll
        for (int v = 0; v < 11; v++) {
            float t = (lane < 8) ? sw2[lane][v] : 0.f;
            #pragma unroll
            for (int off = 4; off > 0; off >>= 1)
                t += __shfl_xor_sync(0xffffffffu, t, off);
            if (lane == 0) tot[v] = t;
        }
    }
    __syncthreads();
    if (tid < 10) out[tid] = (tot[tid] - tot[10]) * (1.0f / (float)N_NODES);
}

// ---------------- launch ----------------
extern "C" void kernel_launch(void* const* d_in, const int* in_sizes, int n_in,
                              void* d_out, int out_size) {
    const float* x  = (const float*)d_in[0];
    const int*   ei = (const int*)d_in[1];
    const float* W1 = (const float*)d_in[2];
    const float* b1 = (const float*)d_in[3];
    const float* W2 = (const float*)d_in[4];
    const float* b2 = (const float*)d_in[5];
    float* out = (float*)d_out;

    cudaFuncSetAttribute(k_mlp, cudaFuncAttributeMaxDynamicSharedMemorySize, SMEM_MLP);

    k_pre<<<NB_E4 + NB_W1 + NB_W2, 256>>>(ei, W1, W2);
    k_scan<<<NB_NODES, 256>>>();
    k_fill<<<NB_E4 + NB_CVT, 256>>>(ei, x);
    k_aggx<<<(N_NODES * 32 + 255) / 256, 256>>>();
    k_mlp<<<MLP_BLOCKS, 256, SMEM_MLP>>>(b1);
    k_final<<<NB_NODES, 256>>>(b2, out);
}

// round 14
// speedup vs baseline: 1.0415x; 1.0415x over previous
#include <cuda_runtime.h>
#include <cuda_bf16.h>
#include <cstdint>

#define N_NODES 100000
#define N_EDGES 1600000
#define IN_F    64
#define HID     128
#define N_CLS   10

#define NB_NODES ((N_NODES + 255) / 256)     // 391
#define NB_E4    (N_EDGES / 4 / 256 + 1)     // 1563
#define N_QUADS  (N_EDGES / 4)               // 400000
#define NB_CVT   (N_NODES * IN_F / (256*4))  // 6250
#define NB_W1    16
#define NB_W2    4

#define MLP_BLOCKS ((N_NODES + 127) / 128)   // 782

// ---------------- device scratch ----------------
__device__ int            g_deg[N_NODES];    // zero-init; re-zeroed by k_fill
__device__ int            g_ptr[N_NODES + 1];
__device__ float          g_dis[N_NODES];
__device__ int            g_srcs[N_EDGES];
__device__ unsigned short g_rank[N_EDGES];
__device__ int            g_bsum[NB_NODES];
__device__ unsigned       g_sync;            // scan grid-barrier counter (reset by k_fill)
__device__ unsigned       g_xh[(size_t)N_NODES * 32];  // xs = dis*x, bf16x2 (12.8 MB)
__device__ unsigned       g_aggh[(size_t)N_NODES * 32];// \hat{A}x bf16x2 (12.8 MB)
__device__ unsigned       g_w1p[32 * 128];
__device__ unsigned       g_w2p[64 * 16];
__device__ unsigned       g_zh[(size_t)N_NODES * 8];   // zs = dis*z, bf16, 16-col pad
__device__ float          g_part[NB_NODES * 11];
__device__ unsigned       g_done;

__device__ __forceinline__ unsigned packbf(float a, float b) {
    __nv_bfloat162 t = __floats2bfloat162_rn(a, b);
    return *(unsigned*)&t;
}
__device__ __forceinline__ float2 unpackbf(unsigned u) {
    return __bfloat1622float2(*(__nv_bfloat162*)&u);
}
__device__ __forceinline__ uint32_t su32(const void* p) {
    return (uint32_t)__cvta_generic_to_shared(p);
}
__device__ __forceinline__ void ldmatrix4(uint32_t& a0, uint32_t& a1, uint32_t& a2, uint32_t& a3, uint32_t addr) {
    asm volatile("ldmatrix.sync.aligned.m8n8.x4.shared.b16 {%0,%1,%2,%3}, [%4];"
                 : "=r"(a0), "=r"(a1), "=r"(a2), "=r"(a3) : "r"(addr));
}
__device__ __forceinline__ void mma16816(float* c, uint32_t a0, uint32_t a1, uint32_t a2, uint32_t a3,
                                         uint32_t b0, uint32_t b1) {
    asm volatile("mma.sync.aligned.m16n8k16.row.col.f32.bf16.bf16.f32 "
                 "{%0,%1,%2,%3},{%4,%5,%6,%7},{%8,%9},{%0,%1,%2,%3};"
                 : "+f"(c[0]), "+f"(c[1]), "+f"(c[2]), "+f"(c[3])
                 : "r"(a0), "r"(a1), "r"(a2), "r"(a3), "r"(b0), "r"(b1));
}

// ---------------- K1: degree histogram (4 edges/thread, ranks) + W pack ------
__global__ void k_pre(const int* __restrict__ ei,
                      const float* __restrict__ W1, const float* __restrict__ W2) {
    int b = blockIdx.x;
    if (b < NB_E4) {
        int q = b * 256 + threadIdx.x;
        if (q < N_QUADS) {
            int4 c = ((const int4*)(ei + N_EDGES))[q];
            int rk[4];
            rk[0] = ((unsigned)c.x < (unsigned)N_NODES) ? atomicAdd(&g_deg[c.x], 1) : 0;
            rk[1] = ((unsigned)c.y < (unsigned)N_NODES) ? atomicAdd(&g_deg[c.y], 1) : 0;
            rk[2] = ((unsigned)c.z < (unsigned)N_NODES) ? atomicAdd(&g_deg[c.z], 1) : 0;
            rk[3] = ((unsigned)c.w < (unsigned)N_NODES) ? atomicAdd(&g_deg[c.w], 1) : 0;
            ushort4 r4;
            r4.x = (unsigned short)rk[0];
            r4.y = (unsigned short)rk[1];
            r4.z = (unsigned short)rk[2];
            r4.w = (unsigned short)rk[3];
            ((ushort4*)g_rank)[q] = r4;
        }
    } else if (b < NB_E4 + NB_W1) {
        int t = (b - NB_E4) * 256 + threadIdx.x;
        int k2 = t >> 7, n = t & 127;
        g_w1p[t] = packbf(W1[(2 * k2) * HID + n], W1[(2 * k2 + 1) * HID + n]);
    } else {
        int t = (b - NB_E4 - NB_W1) * 256 + threadIdx.x;
        int k2 = t >> 4, n = t & 15;
        unsigned v = 0;
        if (n < N_CLS)
            v = packbf(W2[(2 * k2) * N_CLS + n], W2[(2 * k2 + 1) * N_CLS + n]);
        g_w2p[t] = v;
    }
}

// ---------------- K2: FUSED scan (block sums + grid barrier + prefix) --------
__global__ void k_scan() {
    const int tid = threadIdx.x, lane = tid & 31, wid = tid >> 5;
    const int b = blockIdx.x;
    int i = b * 256 + tid;
    int v = (i < N_NODES) ? g_deg[i] : 0;

    int s1 = v;
    #pragma unroll
    for (int o = 16; o > 0; o >>= 1) s1 += __shfl_xor_sync(0xffffffffu, s1, o);
    __shared__ int ws[8];
    __shared__ int wpre[8];
    __shared__ int s_pre;
    if (lane == 0) ws[wid] = s1;
    __syncthreads();
    if (tid == 0) {
        int s = 0;
        #pragma unroll
        for (int w = 0; w < 8; w++) s += ws[w];
        g_bsum[b] = s;
        __threadfence();
        atomicAdd(&g_sync, 1u);
        while (*(volatile unsigned*)&g_sync < (unsigned)NB_NODES) { }
    }
    __syncthreads();
    __threadfence();

    int pre = 0;
    for (int bb = tid; bb < b; bb += 256) pre += __ldcg(&g_bsum[bb]);
    #pragma unroll
    for (int o = 16; o > 0; o >>= 1) pre += __shfl_xor_sync(0xffffffffu, pre, o);
    if (lane == 0) wpre[wid] = pre;
    __syncthreads();
    if (tid == 0) {
        int s = 0;
        #pragma unroll
        for (int w = 0; w < 8; w++) s += wpre[w];
        s_pre = s;
    }
    __syncthreads();
    int prefix = s_pre;

    int x = v;
    #pragma unroll
    for (int o = 1; o < 32; o <<= 1) {
        int t = __shfl_up_sync(0xffffffffu, x, o);
        if (lane >= o) x += t;
    }
    if (lane == 31) ws[wid] = x;
    __syncthreads();
    if (wid == 0 && lane < 8) {
        int t = ws[lane];
        #pragma unroll
        for (int o = 1; o < 8; o <<= 1) {
            int u = __shfl_up_sync(0x000000ffu, t, o);
            if (lane >= o) t += u;
        }
        ws[lane] = t;
    }
    __syncthreads();
    int incl = x + (wid > 0 ? ws[wid - 1] : 0);
    int excl = prefix + incl - v;
    if (i < N_NODES) {
        g_ptr[i] = excl;
        g_dis[i] = rsqrtf((float)(v + 1));
    }
    if (b == NB_NODES - 1 && tid == 255)
        g_ptr[N_NODES] = prefix + incl;
}

// ---------------- K3: atomic-free CSR fill (4 edges/thread) + bf16 convert ---
__global__ void k_fill(const int* __restrict__ ei, const float* __restrict__ x) {
    int b = blockIdx.x;
    if (b < NB_E4) {
        int q = b * 256 + threadIdx.x;
        if (q < N_NODES) g_deg[q] = 0;         // reset for next replay
        if (q == N_QUADS) g_sync = 0;          // reset scan barrier counter
        if (q < N_QUADS) {
            int4 r = ((const int4*)ei)[q];
            int4 c = ((const int4*)(ei + N_EDGES))[q];
            ushort4 rk = ((const ushort4*)g_rank)[q];
            int p0 = ((unsigned)c.x < (unsigned)N_NODES) ? g_ptr[c.x] + rk.x : -1;
            int p1 = ((unsigned)c.y < (unsigned)N_NODES) ? g_ptr[c.y] + rk.y : -1;
            int p2 = ((unsigned)c.z < (unsigned)N_NODES) ? g_ptr[c.z] + rk.z : -1;
            int p3 = ((unsigned)c.w < (unsigned)N_NODES) ? g_ptr[c.w] + rk.w : -1;
            if (p0 >= 0 && (unsigned)r.x < (unsigned)N_NODES) g_srcs[p0] = r.x;
            if (p1 >= 0 && (unsigned)r.y < (unsigned)N_NODES) g_srcs[p1] = r.y;
            if (p2 >= 0 && (unsigned)r.z < (unsigned)N_NODES) g_srcs[p2] = r.z;
            if (p3 >= 0 && (unsigned)r.w < (unsigned)N_NODES) g_srcs[p3] = r.w;
        }
    } else {
        int i = (b - NB_E4) * 256 + threadIdx.x;   // 1.6M threads, 4 floats each
        float d = g_dis[i >> 4];
        float4 v = ((const float4*)x)[i];
        uint2 pk;
        pk.x = packbf(d * v.x, d * v.y);
        pk.y = packbf(d * v.z, d * v.w);
        ((uint2*)g_xh)[i] = pk;
    }
}

// ---------------- K4: agg gather — unroll 8, 64-reg budget, 32-bit idx -------
__global__ void __launch_bounds__(256, 4) k_aggx() {
    int warp = (blockIdx.x * blockDim.x + threadIdx.x) >> 5;
    int lane = threadIdx.x & 31;
    if (warp >= N_NODES) return;
    float di = g_dis[warp];
    float2 acc = unpackbf(g_xh[(unsigned)warp * 32u + lane]);   // xs_i (self-loop)
    int p = g_ptr[warp], e = g_ptr[warp + 1];
    for (; p + 8 <= e; p += 8) {
        int r[8];
        #pragma unroll
        for (int j = 0; j < 8; j++) r[j] = g_srcs[p + j];
        unsigned u[8];
        #pragma unroll
        for (int j = 0; j < 8; j++) u[j] = g_xh[(unsigned)r[j] * 32u + lane];
        #pragma unroll
        for (int j = 0; j < 8; j++) {
            float2 t = unpackbf(u[j]);
            acc.x += t.x; acc.y += t.y;
        }
    }
    for (; p + 2 <= e; p += 2) {
        int r0 = g_srcs[p], r1 = g_srcs[p + 1];
        unsigned u0 = g_xh[(unsigned)r0 * 32u + lane];
        unsigned u1 = g_xh[(unsigned)r1 * 32u + lane];
        float2 t0 = unpackbf(u0), t1 = unpackbf(u1);
        acc.x += t0.x + t1.x;
        acc.y += t0.y + t1.y;
    }
    if (p < e) {
        int r = g_srcs[p];
        float2 t = unpackbf(g_xh[(unsigned)r * 32u + lane]);
        acc.x += t.x; acc.y += t.y;
    }
    g_aggh[(unsigned)warp * 32u + lane] = packbf(di * acc.x, di * acc.y);
}

// ---------------- K5: tensor-core MLP; z written premultiplied by dis --------
#define SA_STRIDE 136
#define W1_STRIDE 136
#define W2_STRIDE 40
#define SMEM_MLP ((32*W1_STRIDE + 64*W2_STRIDE + 128) * 4 + 128 * SA_STRIDE * 2)

__global__ void __launch_bounds__(256) k_mlp(const float* __restrict__ b1) {
    extern __shared__ __align__(16) unsigned char smem_raw[];
    unsigned* sW1p = (unsigned*)smem_raw;
    unsigned* sW2p = sW1p + 32 * W1_STRIDE;
    float*    sb1  = (float*)(sW2p + 64 * W2_STRIDE);
    __nv_bfloat16* sAh = (__nv_bfloat16*)(sb1 + 128);

    const int tid = threadIdx.x;
    const int w = tid >> 5, l = tid & 31;
    const int row0 = blockIdx.x * 128;

    for (int t = tid; t < 32 * 128; t += 256)
        sW1p[(t >> 7) * W1_STRIDE + (t & 127)] = g_w1p[t];
    for (int t = tid; t < 64 * 16; t += 256)
        sW2p[(t >> 4) * W2_STRIDE + (t & 15)] = g_w2p[t];
    if (tid < 128) sb1[tid] = b1[tid];
    for (int t = tid; t < 1024; t += 256) {
        int row = t >> 3, q = t & 7;
        int gr = row0 + row;
        uint4 v = make_uint4(0, 0, 0, 0);
        if (gr < N_NODES) v = ((const uint4*)g_aggh)[(size_t)gr * 8 + q];
        *(uint4*)((char*)sAh + row * (SA_STRIDE * 2) + q * 16) = v;
    }
    __syncthreads();

    const int lrow = l >> 2;
    const int colb = (l & 3) * 2;
    const int nb = l >> 2;
    const uint32_t a_base = su32(sAh) + (uint32_t)(((w * 16 + (l & 15)) * SA_STRIDE + ((l >> 4) * 8)) * 2);

    float acc[16][4];
    #pragma unroll
    for (int nt = 0; nt < 16; nt++)
        #pragma unroll
        for (int j = 0; j < 4; j++) acc[nt][j] = 0.f;

    #pragma unroll
    for (int kk = 0; kk < 4; kk++) {
        uint32_t a0, a1, a2, a3;
        ldmatrix4(a0, a1, a2, a3, a_base + kk * 32);
        int k2b = kk * 8 + (l & 3);
        #pragma unroll
        for (int nt = 0; nt < 16; nt++) {
            unsigned bf0 = sW1p[k2b * W1_STRIDE + nt * 8 + nb];
            unsigned bf1 = sW1p[(k2b + 4) * W1_STRIDE + nt * 8 + nb];
            mma16816(acc[nt], a0, a1, a2, a3, bf0, bf1);
        }
    }
    __syncthreads();

    const int hrow0 = w * 16 + lrow;
    #pragma unroll
    for (int nt = 0; nt < 16; nt++) {
        float bb0 = sb1[nt * 8 + colb];
        float bb1 = sb1[nt * 8 + colb + 1];
        float c0 = fmaxf(acc[nt][0] + bb0, 0.f);
        float c1 = fmaxf(acc[nt][1] + bb1, 0.f);
        float c2 = fmaxf(acc[nt][2] + bb0, 0.f);
        float c3 = fmaxf(acc[nt][3] + bb1, 0.f);
        *(unsigned*)((char*)sAh + (hrow0 * SA_STRIDE + nt * 8 + colb) * 2) = packbf(c0, c1);
        *(unsigned*)((char*)sAh + ((hrow0 + 8) * SA_STRIDE + nt * 8 + colb) * 2) = packbf(c2, c3);
    }
    __syncwarp();

    float acc2[2][4];
    #pragma unroll
    for (int nt = 0; nt < 2; nt++)
        #pragma unroll
        for (int j = 0; j < 4; j++) acc2[nt][j] = 0.f;

    #pragma unroll
    for (int kk = 0; kk < 8; kk++) {
        uint32_t a0, a1, a2, a3;
        ldmatrix4(a0, a1, a2, a3, a_base + kk * 32);
        int k2b = kk * 8 + (l & 3);
        #pragma unroll
        for (int nt = 0; nt < 2; nt++) {
            unsigned bf0 = sW2p[k2b * W2_STRIDE + nt * 8 + nb];
            unsigned bf1 = sW2p[(k2b + 4) * W2_STRIDE + nt * 8 + nb];
            mma16816(acc2[nt], a0, a1, a2, a3, bf0, bf1);
        }
    }

    int gr0 = row0 + w * 16 + lrow;
    int gr1 = gr0 + 8;
    int cq = l & 3;
    if (gr0 < N_NODES) {
        float d0 = g_dis[gr0];
        g_zh[(size_t)gr0 * 8 + cq] = packbf(d0 * acc2[0][0], d0 * acc2[0][1]);
        g_zh[(size_t)gr0 * 8 + 4 + cq] = (cq == 0) ? packbf(d0 * acc2[1][0], d0 * acc2[1][1]) : 0u;
    }
    if (gr1 < N_NODES) {
        float d1 = g_dis[gr1];
        g_zh[(size_t)gr1 * 8 + cq] = packbf(d1 * acc2[0][2], d1 * acc2[0][3]);
        g_zh[(size_t)gr1 * 8 + 4 + cq] = (cq == 0) ? packbf(d1 * acc2[1][2], d1 * acc2[1][3]) : 0u;
    }
}

// ---------------- K6: a = d_i*(zs_i + sum zs_r) + b2; log_softmax; reduce ----
__device__ __forceinline__ void add_row(float* a, const uint4 v0, const uint2 v1) {
    float2 t;
    t = unpackbf(v0.x); a[0] += t.x; a[1] += t.y;
    t = unpackbf(v0.y); a[2] += t.x; a[3] += t.y;
    t = unpackbf(v0.z); a[4] += t.x; a[5] += t.y;
    t = unpackbf(v0.w); a[6] += t.x; a[7] += t.y;
    t = unpackbf(v1.x); a[8] += t.x; a[9] += t.y;
}

__global__ void k_final(const float* __restrict__ b2, float* __restrict__ out) {
    const int tid = threadIdx.x, lane = tid & 31, wid = tid >> 5;
    int i = blockIdx.x * blockDim.x + tid;
    float vals[11];
    #pragma unroll
    for (int v = 0; v < 11; v++) vals[v] = 0.f;

    if (i < N_NODES) {
        const uint4* z4 = (const uint4*)g_zh;
        const uint2* z2 = (const uint2*)g_zh;
        float di = g_dis[i];
        float a[10];
        #pragma unroll
        for (int c = 0; c < 10; c++) a[c] = 0.f;
        add_row(a, z4[(size_t)i * 2], z2[(size_t)i * 4 + 2]);
        int p = g_ptr[i], e = g_ptr[i + 1];
        for (; p + 4 <= e; p += 4) {
            int r[4];
            #pragma unroll
            for (int j = 0; j < 4; j++) r[j] = g_srcs[p + j];
            uint4 u[4];
            uint2 w4[4];
            #pragma unroll
            for (int j = 0; j < 4; j++) {
                u[j] = z4[(size_t)r[j] * 2];
                w4[j] = z2[(size_t)r[j] * 4 + 2];
            }
            #pragma unroll
            for (int j = 0; j < 4; j++) add_row(a, u[j], w4[j]);
        }
        for (; p < e; ++p) {
            int r = g_srcs[p];
            add_row(a, z4[(size_t)r * 2], z2[(size_t)r * 4 + 2]);
        }
        float mx = -1e30f;
        #pragma unroll
        for (int c = 0; c < 10; c++) { a[c] = di * a[c] + b2[c]; mx = fmaxf(mx, a[c]); }
        float se = 0.f;
        #pragma unroll
        for (int c = 0; c < 10; c++) se += expf(a[c] - mx);
        float lse = mx + logf(se);
        #pragma unroll
        for (int c = 0; c < 10; c++) vals[c] = a[c];
        vals[10] = lse;
    }

    #pragma unroll
    for (int v = 0; v < 11; v++)
        #pragma unroll
        for (int off = 16; off > 0; off >>= 1)
            vals[v] += __shfl_xor_sync(0xffffffffu, vals[v], off);

    __shared__ float sw[8][11];
    if (lane == 0)
        #pragma unroll
        for (int v = 0; v < 11; v++) sw[wid][v] = vals[v];
    __syncthreads();
    if (wid == 0) {
        #pragma unroll
        for (int v = 0; v < 11; v++) {
            float t = (lane < 8) ? sw[lane][v] : 0.f;
            #pragma unroll
            for (int off = 4; off > 0; off >>= 1)
                t += __shfl_xor_sync(0xffffffffu, t, off);
            if (lane == 0) g_part[blockIdx.x * 11 + v] = t;
        }
    }

    __shared__ bool s_last;
    __threadfence();
    if (tid == 0) {
        unsigned ticket = atomicAdd(&g_done, 1u);
        s_last = (ticket == (unsigned)(gridDim.x - 1));
        if (s_last) g_done = 0;
    }
    __syncthreads();
    if (!s_last) return;

    const volatile float* vp = (const volatile float*)g_part;
    float s[11];
    #pragma unroll
    for (int v = 0; v < 11; v++) {
        float t = 0.f;
        for (int b = tid; b < NB_NODES; b += 256) t += vp[b * 11 + v];
        s[v] = t;
    }
    #pragma unroll
    for (int v = 0; v < 11; v++)
        #pragma unroll
        for (int off = 16; off > 0; off >>= 1)
            s[v] += __shfl_xor_sync(0xffffffffu, s[v], off);

    __shared__ float sw2[8][11];
    __shared__ float tot[11];
    if (lane == 0)
        #pragma unroll
        for (int v = 0; v < 11; v++) sw2[wid][v] = s[v];
    __syncthreads();
    if (wid == 0) {
        #pragma unroll
        for (int v = 0; v < 11; v++) {
            float t = (lane < 8) ? sw2[lane][v] : 0.f;
            #pragma unroll
            for (int off = 4; off > 0; off >>= 1)
                t += __shfl_xor_sync(0xffffffffu, t, off);
            if (lane == 0) tot[v] = t;
        }
    }
    __syncthreads();
    if (tid < 10) out[tid] = (tot[tid] - tot[10]) * (1.0f / (float)N_NODES);
}

// ---------------- launch ----------------
extern "C" void kernel_launch(void* const* d_in, const int* in_sizes, int n_in,
                              void* d_out, int out_size) {
    const float* x  = (const float*)d_in[0];
    const int*   ei = (const int*)d_in[1];
    const float* W1 = (const float*)d_in[2];
    const float* b1 = (const float*)d_in[3];
    const float* W2 = (const float*)d_in[4];
    const float* b2 = (const float*)d_in[5];
    float* out = (float*)d_out;

    cudaFuncSetAttribute(k_mlp, cudaFuncAttributeMaxDynamicSharedMemorySize, SMEM_MLP);

    k_pre<<<NB_E4 + NB_W1 + NB_W2, 256>>>(ei, W1, W2);
    k_scan<<<NB_NODES, 256>>>();
    k_fill<<<NB_E4 + NB_CVT, 256>>>(ei, x);
    k_aggx<<<(N_NODES * 32 + 255) / 256, 256>>>();
    k_mlp<<<MLP_BLOCKS, 256, SMEM_MLP>>>(b1);
    k_final<<<NB_NODES, 256>>>(b2, out);
}